// round 2
// baseline (speedup 1.0000x reference)
#include <cuda_runtime.h>
#include <cuda_bf16.h>
#include <mma.h>
#include <cstdint>

using namespace nvcuda;

// ---------------------------------------------------------------------------
// MambaRefiner: B=2, C=64, T=512, CH=8, D_MODEL=512, D_IN=1024, D_ST=128,
// DT_R=32, K=3, L=2.  fp32 I/O, tf32 tensor-core GEMMs.
// ---------------------------------------------------------------------------

#define NB 2
#define NT 512
#define DMODEL 512
#define DIN 1024
#define NROWS (NB * NT)          // 1024 tokens

// scratch layout (floats)
#define OFF_H     0                       // 1024 x 512
#define OFF_XZ    (OFF_H + NROWS*DMODEL)  // 1024 x 2048
#define OFF_XS    (OFF_XZ + NROWS*2*DIN)  // 1024 x 1024
#define OFF_XDBL  (OFF_XS + NROWS*DIN)    // 1024 x 288
#define OFF_DELTA (OFF_XDBL + NROWS*288)  // 1024 x 1024
#define OFF_Y     (OFF_DELTA + NROWS*DIN) // 1024 x 1024
#define SCRATCH_TOTAL (OFF_Y + NROWS*DIN)

__device__ float g_scratch[SCRATCH_TOTAL];

// ---------------------------------------------------------------------------
// Input transpose: h[b,t,c*8+ch] = z_q[b,c,t,ch]
// ---------------------------------------------------------------------------
__global__ void k_transpose_in(const float* __restrict__ zq, float* __restrict__ h) {
    int idx = blockIdx.x * blockDim.x + threadIdx.x;
    int d = idx & 511;
    int r = idx >> 9;
    int t = r & 511;
    int b = r >> 9;
    h[idx] = zq[((b * 64 + (d >> 3)) * 512 + t) * 8 + (d & 7)];
}

// ---------------------------------------------------------------------------
// Causal depthwise conv K=3 + bias + SiLU on x (first DIN cols of xz)
// ---------------------------------------------------------------------------
__global__ void k_conv_silu(const float* __restrict__ xz,
                            const float* __restrict__ cw,
                            const float* __restrict__ cb,
                            float* __restrict__ xs) {
    int idx = blockIdx.x * blockDim.x + threadIdx.x;
    int d = idx & 1023;
    int row = idx >> 10;
    int t = row & 511;
    float v = cb[d] + cw[d * 3 + 2] * xz[row * 2048 + d];
    if (t > 0) v += cw[d * 3 + 1] * xz[(row - 1) * 2048 + d];
    if (t > 1) v += cw[d * 3 + 0] * xz[(row - 2) * 2048 + d];
    xs[idx] = v / (1.0f + __expf(-v));
}

// ---------------------------------------------------------------------------
// tf32 tensor-core GEMM: C[m,n] = sum_k A[m,k] * W[n,k]   (both K-major fp32)
// wmma m16n16k8, fp32 accumulate.
// EPI: 0 = plain store, 1 = softplus(acc + bias[n]), 2 = bias + scatter to
//      (b, c, t, ch) output layout.
// Requires M%BM==0, N%BN==0, K%BK==0, lda/ldw/ldc multiples of 4.
// ---------------------------------------------------------------------------
template<int BM, int BN, int BK, int WM, int WN, int EPI>
__global__ void __launch_bounds__((BM/WM)*(BN/WN)*32)
k_mma(const float* __restrict__ A, int lda,
      const float* __restrict__ W, int ldw,
      float* __restrict__ C, int ldc, int K,
      const float* __restrict__ bias,
      float* __restrict__ out2) {
    constexpr int LDT = BK + 4;                 // smem tile leading dim (mult of 4)
    constexpr int NWN = BN / WN;
    constexpr int NWARP = (BM / WM) * NWN;
    constexpr int NTHR = NWARP * 32;
    constexpr int MI = WM / 16, NI = WN / 16;
    constexpr int LDCS = BN + 4;
    constexpr int SM_LOAD = (BM + BN) * LDT;
    constexpr int SM_EPI = (EPI == 0) ? 0 : BM * LDCS;
    constexpr int SMSZ = SM_LOAD > SM_EPI ? SM_LOAD : SM_EPI;
    __shared__ float sm[SMSZ];
    float* As = sm;
    float* Ws = sm + BM * LDT;

    const int tid = threadIdx.x;
    const int wid = tid >> 5;
    const int wm0 = (wid / NWN) * WM;
    const int wn0 = (wid % NWN) * WN;
    const int m0 = blockIdx.y * BM;
    const int n0 = blockIdx.x * BN;

    wmma::fragment<wmma::accumulator, 16, 16, 8, float> acc[MI][NI];
#pragma unroll
    for (int i = 0; i < MI; i++)
#pragma unroll
        for (int j = 0; j < NI; j++) wmma::fill_fragment(acc[i][j], 0.0f);

    for (int k0 = 0; k0 < K; k0 += BK) {
        for (int i = tid; i < BM * (BK / 4); i += NTHR) {
            int r = i / (BK / 4), q = i % (BK / 4);
            float4 v = *(const float4*)&A[(size_t)(m0 + r) * lda + k0 + q * 4];
            *(float4*)&As[r * LDT + q * 4] = v;
        }
        for (int i = tid; i < BN * (BK / 4); i += NTHR) {
            int r = i / (BK / 4), q = i % (BK / 4);
            float4 v = *(const float4*)&W[(size_t)(n0 + r) * ldw + k0 + q * 4];
            *(float4*)&Ws[r * LDT + q * 4] = v;
        }
        __syncthreads();

#pragma unroll
        for (int kk = 0; kk < BK; kk += 8) {
            wmma::fragment<wmma::matrix_a, 16, 16, 8, wmma::precision::tf32, wmma::row_major> fa[MI];
            wmma::fragment<wmma::matrix_b, 16, 16, 8, wmma::precision::tf32, wmma::col_major> fb[NI];
#pragma unroll
            for (int i = 0; i < MI; i++) {
                wmma::load_matrix_sync(fa[i], &As[(wm0 + 16 * i) * LDT + kk], LDT);
#pragma unroll
                for (int e = 0; e < fa[i].num_elements; e++)
                    fa[i].x[e] = wmma::__float_to_tf32(fa[i].x[e]);
            }
#pragma unroll
            for (int j = 0; j < NI; j++) {
                wmma::load_matrix_sync(fb[j], &Ws[(wn0 + 16 * j) * LDT + kk], LDT);
#pragma unroll
                for (int e = 0; e < fb[j].num_elements; e++)
                    fb[j].x[e] = wmma::__float_to_tf32(fb[j].x[e]);
            }
#pragma unroll
            for (int i = 0; i < MI; i++)
#pragma unroll
                for (int j = 0; j < NI; j++)
                    wmma::mma_sync(acc[i][j], fa[i], fb[j], acc[i][j]);
        }
        __syncthreads();
    }

    if (EPI == 0) {
#pragma unroll
        for (int i = 0; i < MI; i++)
#pragma unroll
            for (int j = 0; j < NI; j++)
                wmma::store_matrix_sync(&C[(size_t)(m0 + wm0 + 16 * i) * ldc + n0 + wn0 + 16 * j],
                                        acc[i][j], ldc, wmma::mem_row_major);
    } else {
        // stage to smem, apply epilogue elementwise
#pragma unroll
        for (int i = 0; i < MI; i++)
#pragma unroll
            for (int j = 0; j < NI; j++)
                wmma::store_matrix_sync(&sm[(wm0 + 16 * i) * LDCS + wn0 + 16 * j],
                                        acc[i][j], LDCS, wmma::mem_row_major);
        __syncthreads();
        for (int i = tid; i < BM * BN; i += NTHR) {
            int r = i / BN, c = i % BN;
            int row = m0 + r, col = n0 + c;
            float v = sm[r * LDCS + c] + bias[col];
            if (EPI == 1) {
                float sp = (v > 20.0f) ? v : log1pf(__expf(v));
                C[(size_t)row * ldc + col] = sp;
            } else { // EPI == 2: scatter to (b, c, t, ch)
                int b = row >> 9;
                int t = row & 511;
                out2[b * 262144 + (col >> 3) * 4096 + t * 8 + (col & 7)] = v;
            }
        }
    }
}

// ---------------------------------------------------------------------------
// Selective scan.  grid = (128, 2): blockIdx.y = batch, 8 warps/block,
// warp w handles channel d = blockIdx.x*8 + w, 4 states per lane.
// ---------------------------------------------------------------------------
__global__ void __launch_bounds__(256)
k_scan(const float* __restrict__ xdbl,    // (1024, 288): [dt | B | C]
       const float* __restrict__ delta,   // (1024, 1024)
       const float* __restrict__ xs,      // (1024, 1024)
       const float* __restrict__ xz,      // (1024, 2048), z = cols [1024:2048)
       const float* __restrict__ alog,    // (1024, 128)
       const float* __restrict__ Dp,      // (1024,)
       float* __restrict__ y) {           // (1024, 1024)
    const int b = blockIdx.y;
    const int w = threadIdx.x >> 5;
    const int lane = threadIdx.x & 31;
    const int d = blockIdx.x * 8 + w;

    __shared__ float Bs[32][128];
    __shared__ float Cs[32][128];
    __shared__ float dsh[32][8];
    __shared__ float xsh[32][8];
    __shared__ float zsh[32][8];

    const float* Ap = alog + d * 128 + lane * 4;
    float A0 = -expf(Ap[0]);
    float A1 = -expf(Ap[1]);
    float A2 = -expf(Ap[2]);
    float A3 = -expf(Ap[3]);
    float Dd = Dp[d];

    float h0 = 0.f, h1 = 0.f, h2 = 0.f, h3 = 0.f;
    const int rowbase = b * 512;

    for (int tc = 0; tc < 512; tc += 32) {
        for (int i = threadIdx.x; i < 32 * 32; i += 256) {
            int tt = i >> 5, sq = i & 31;
            int row = rowbase + tc + tt;
            *(float4*)&Bs[tt][sq * 4] = *(const float4*)&xdbl[row * 288 + 32 + sq * 4];
            *(float4*)&Cs[tt][sq * 4] = *(const float4*)&xdbl[row * 288 + 160 + sq * 4];
        }
        if (threadIdx.x < 32 * 8) {
            int tt = threadIdx.x >> 3, dd = threadIdx.x & 7;
            int row = rowbase + tc + tt;
            int dcol = blockIdx.x * 8 + dd;
            dsh[tt][dd] = delta[row * 1024 + dcol];
            xsh[tt][dd] = xs[row * 1024 + dcol];
            zsh[tt][dd] = xz[row * 2048 + 1024 + dcol];
        }
        __syncthreads();

        for (int tt = 0; tt < 32; tt++) {
            float dv = dsh[tt][w];
            float xv = xsh[tt][w];
            float dx = dv * xv;
            float4 Bv = *(float4*)&Bs[tt][lane * 4];
            float4 Cv = *(float4*)&Cs[tt][lane * 4];
            h0 = __expf(dv * A0) * h0 + dx * Bv.x;
            h1 = __expf(dv * A1) * h1 + dx * Bv.y;
            h2 = __expf(dv * A2) * h2 + dx * Bv.z;
            h3 = __expf(dv * A3) * h3 + dx * Bv.w;
            float acc = h0 * Cv.x + h1 * Cv.y + h2 * Cv.z + h3 * Cv.w;
            acc += __shfl_xor_sync(0xffffffffu, acc, 16);
            acc += __shfl_xor_sync(0xffffffffu, acc, 8);
            acc += __shfl_xor_sync(0xffffffffu, acc, 4);
            acc += __shfl_xor_sync(0xffffffffu, acc, 2);
            acc += __shfl_xor_sync(0xffffffffu, acc, 1);
            if (lane == 0) {
                float yy = acc + xv * Dd;
                float zv = zsh[tt][w];
                float sz = zv / (1.0f + __expf(-zv));
                y[(rowbase + tc + tt) * 1024 + d] = yy * sz;
            }
        }
        __syncthreads();
    }
}

// ---------------------------------------------------------------------------
extern "C" void kernel_launch(void* const* d_in, const int* in_sizes, int n_in,
                              void* d_out, int out_size) {
    const float* z_q  = (const float*)d_in[0];
    const float* ipw  = (const float*)d_in[1];   // (2, 2048, 512)
    const float* cw   = (const float*)d_in[2];   // (2, 1024, 3)
    const float* cb   = (const float*)d_in[3];   // (2, 1024)
    const float* xpw  = (const float*)d_in[4];   // (2, 288, 1024)
    const float* dpw  = (const float*)d_in[5];   // (2, 1024, 32)
    const float* dpb  = (const float*)d_in[6];   // (2, 1024)
    const float* alog = (const float*)d_in[7];   // (2, 1024, 128)
    const float* Dp   = (const float*)d_in[8];   // (2, 1024)
    const float* opw  = (const float*)d_in[9];   // (2, 512, 1024)
    const float* fcw  = (const float*)d_in[10];  // (512, 512)
    const float* fcb  = (const float*)d_in[11];  // (512,)
    float* out = (float*)d_out;

    float* S = nullptr;
    cudaGetSymbolAddress((void**)&S, g_scratch);
    float* H  = S + OFF_H;
    float* XZ = S + OFF_XZ;
    float* XS = S + OFF_XS;
    float* XD = S + OFF_XDBL;
    float* DL = S + OFF_DELTA;
    float* Y  = S + OFF_Y;

    k_transpose_in<<<NROWS * DMODEL / 256, 256>>>(z_q, H);

    for (int l = 0; l < 2; l++) {
        // xz = H @ ipw^T : (1024, 2048), K=512
        k_mma<128, 128, 32, 32, 64, 0><<<dim3(2048 / 128, 1024 / 128), 256>>>(
            H, 512, ipw + l * 2048 * 512, 512, XZ, 2048, 512, nullptr, nullptr);

        // conv + silu -> XS (1024, 1024)
        k_conv_silu<<<NROWS * DIN / 256, 256>>>(XZ, cw + l * 1024 * 3, cb + l * 1024, XS);

        // x_dbl = XS @ xpw^T : (1024, 288), K=1024
        k_mma<64, 32, 32, 32, 16, 0><<<dim3(288 / 32, 1024 / 64), 128>>>(
            XS, 1024, xpw + l * 288 * 1024, 1024, XD, 288, 1024, nullptr, nullptr);

        // delta = softplus(dt @ dpw^T + dpb) : (1024, 1024), K=32
        k_mma<64, 64, 32, 32, 32, 1><<<dim3(1024 / 64, 1024 / 64), 128>>>(
            XD, 288, dpw + l * 1024 * 32, 32, DL, 1024, 32, dpb + l * 1024, nullptr);

        // selective scan -> Y
        k_scan<<<dim3(128, 2), 256>>>(XD, DL, XS, XZ,
                                      alog + l * 1024 * 128, Dp + l * 1024, Y);

        // H = Y @ opw^T : (1024, 512), K=1024
        k_mma<64, 64, 32, 32, 32, 0><<<dim3(512 / 64, 1024 / 64), 128>>>(
            Y, 1024, opw + l * 512 * 1024, 1024, H, 512, 1024, nullptr, nullptr);
    }

    // out = (H @ fcw^T + fcb) scattered to (b, c, t, ch), K=512
    k_mma<64, 64, 32, 32, 32, 2><<<dim3(512 / 64, 1024 / 64), 128>>>(
        H, 512, fcw, 512, nullptr, 512, 512, fcb, out);
}